// round 2
// baseline (speedup 1.0000x reference)
#include <cuda_runtime.h>

#define NFC   64
#define HWS   64
#define PSZ   8
#define NB    4
#define NT    16
#define NIMG  64      // NB*NT
#define TOK   1024    // NT * 64 patches
#define DIMD  4096    // NFC * PSZ * PSZ

// ---------------- scratch (static device globals; no allocation) -------------
__device__ __align__(128) float g_Q[NB][TOK][DIMD];
__device__ __align__(128) float g_K[NB][TOK][DIMD];
__device__ __align__(128) float g_V[NB][TOK][DIMD];
__device__ __align__(128) float g_S[NB][TOK][TOK];
__device__ __align__(128) float g_feat[NIMG][NFC][HWS][HWS];
__device__ __align__(128) float g_vwT[576][NFC];   // [(ic*3+ky)*3+kx][oc]
__device__ __align__(128) float g_cwT[576][NFC];

// ---------------- kernel 0: transpose conv weights for vectorized reads ------
__global__ void transpose_w_kernel(const float* __restrict__ vw,
                                   const float* __restrict__ cw) {
    int idx = blockIdx.x * blockDim.x + threadIdx.x;
    if (idx < 64 * 576) {
        int oc = idx / 576;
        int r  = idx - oc * 576;           // ic*9 + ky*3 + kx
        g_vwT[r][oc] = vw[oc * 576 + r];
        g_cwT[r][oc] = cw[oc * 576 + r];
    }
}

// ---------------- kernel 1: q,k depthwise + v full conv, write token layout --
// grid (64 imgs, 8 row-tiles), 512 threads, dyn smem = 64ch * 10rows * 66cols
__global__ __launch_bounds__(512) void qkv_kernel(
    const float* __restrict__ x,
    const float* __restrict__ qw, const float* __restrict__ qb,
    const float* __restrict__ kw, const float* __restrict__ kb,
    const float* __restrict__ vb)
{
    extern __shared__ float s[];          // [64][10][66]
    const int img   = blockIdx.x;
    const int ytile = blockIdx.y;
    const int y0    = ytile * 8;
    const int bb    = img >> 4;
    const int tt    = img & 15;
    const int tid   = threadIdx.x;
    const float* xim = x + (size_t)img * NFC * HWS * HWS;

    // load halo tile
    for (int idx = tid; idx < 64 * 10 * 66; idx += 512) {
        int c  = idx / 660;
        int rr = idx - c * 660;
        int yy = rr / 66;
        int xx = rr - yy * 66;
        int gy = y0 - 1 + yy;
        int gx = xx - 1;
        float v = 0.f;
        if (gy >= 0 && gy < 64 && gx >= 0 && gx < 64)
            v = xim[c * 4096 + gy * 64 + gx];
        s[idx] = v;
    }
    __syncthreads();

    // depthwise q,k: iteration it handles channel c = it, pixel p = tid
    for (int it = 0; it < 64; it++) {
        int c  = it;
        int p  = tid;
        int yy = p >> 6;
        int xx = p & 63;
        const float* sp = s + c * 660 + yy * 66 + xx;
        float aq = 0.f, ak = 0.f;
        #pragma unroll
        for (int ky = 0; ky < 3; ky++)
            #pragma unroll
            for (int kx = 0; kx < 3; kx++) {
                float xv = sp[ky * 66 + kx];
                aq = fmaf(xv, qw[c * 9 + ky * 3 + kx], aq);
                ak = fmaf(xv, kw[c * 9 + ky * 3 + kx], ak);
            }
        aq += qb[c];
        ak += kb[c];
        int tok = tt * 64 + ytile * 8 + (xx >> 3);
        int d   = c * 64 + yy * 8 + (xx & 7);
        g_Q[bb][tok][d] = aq;
        g_K[bb][tok][d] = ak;
    }

    // v full conv: thread tile 8 px (one patch row) x 8 oc
    const int ocg = tid & 7;
    const int pg  = tid >> 3;
    const int oc0 = ocg << 3;
    const int py  = pg >> 3;                 // 0..7 (row within tile)
    const int x0  = (pg & 7) << 3;           // patch column * 8
    float acc[8][8];
    #pragma unroll
    for (int i = 0; i < 8; i++)
        #pragma unroll
        for (int j = 0; j < 8; j++) acc[i][j] = 0.f;

    const float4* wt4 = reinterpret_cast<const float4*>(&g_vwT[0][0]);
    const int wb = oc0 >> 2;
    for (int ic = 0; ic < 64; ic++) {
        const float* sc = s + ic * 660 + py * 66 + x0;
        const float4* wr = wt4 + ic * 144 + wb;      // 9 taps * 16 float4 per row
        #pragma unroll
        for (int kk = 0; kk < 9; kk++) {
            const int ky = kk / 3;
            const int kx = kk - ky * 3;
            float4 w0 = wr[kk * 16];
            float4 w1 = wr[kk * 16 + 1];
            float wv[8] = {w0.x, w0.y, w0.z, w0.w, w1.x, w1.y, w1.z, w1.w};
            const float* sp = sc + ky * 66 + kx;
            #pragma unroll
            for (int i = 0; i < 8; i++) {
                float xv = sp[i];
                #pragma unroll
                for (int j = 0; j < 8; j++)
                    acc[i][j] = fmaf(xv, wv[j], acc[i][j]);
            }
        }
    }

    const int tok = tt * 64 + ytile * 8 + (pg & 7);
    float* vrow = &g_V[bb][tok][0];
    #pragma unroll
    for (int j = 0; j < 8; j++) {
        int   oc   = oc0 + j;
        float bias = vb[oc];
        int   d    = oc * 64 + py * 8;
        float4 o0 = make_float4(acc[0][j] + bias, acc[1][j] + bias,
                                acc[2][j] + bias, acc[3][j] + bias);
        float4 o1 = make_float4(acc[4][j] + bias, acc[5][j] + bias,
                                acc[6][j] + bias, acc[7][j] + bias);
        *(float4*)&vrow[d]     = o0;
        *(float4*)&vrow[d + 4] = o1;
    }
}

// ---------------- kernel 2: S = (Q K^T) * d^-0.5, NT SGEMM 128x128x8 ---------
__global__ __launch_bounds__(256, 2) void gemm_qk_kernel() {
    __shared__ float As[8][128];
    __shared__ float Bs[8][128];
    const int b  = blockIdx.z;
    const int i0 = blockIdx.y * 128;
    const int j0 = blockIdx.x * 128;
    const int tid = threadIdx.x;
    const int tx = tid & 15;
    const int ty = tid >> 4;
    const float* A  = &g_Q[b][0][0];
    const float* Bm = &g_K[b][0][0];
    const int lr = tid >> 1;
    const int lc = (tid & 1) << 2;
    float acc[8][8];
    #pragma unroll
    for (int i = 0; i < 8; i++)
        #pragma unroll
        for (int j = 0; j < 8; j++) acc[i][j] = 0.f;

    float4 va = *(const float4*)&A [(i0 + lr) * DIMD + lc];
    float4 vb = *(const float4*)&Bm[(j0 + lr) * DIMD + lc];
    for (int k0 = 0; k0 < DIMD; k0 += 8) {
        As[lc + 0][lr] = va.x; As[lc + 1][lr] = va.y;
        As[lc + 2][lr] = va.z; As[lc + 3][lr] = va.w;
        Bs[lc + 0][lr] = vb.x; Bs[lc + 1][lr] = vb.y;
        Bs[lc + 2][lr] = vb.z; Bs[lc + 3][lr] = vb.w;
        __syncthreads();
        if (k0 + 8 < DIMD) {
            va = *(const float4*)&A [(i0 + lr) * DIMD + k0 + 8 + lc];
            vb = *(const float4*)&Bm[(j0 + lr) * DIMD + k0 + 8 + lc];
        }
        #pragma unroll
        for (int kk = 0; kk < 8; kk++) {
            float a[8], bv[8];
            *(float4*)&a[0]  = *(const float4*)&As[kk][ty * 8];
            *(float4*)&a[4]  = *(const float4*)&As[kk][ty * 8 + 4];
            *(float4*)&bv[0] = *(const float4*)&Bs[kk][tx * 8];
            *(float4*)&bv[4] = *(const float4*)&Bs[kk][tx * 8 + 4];
            #pragma unroll
            for (int i = 0; i < 8; i++)
                #pragma unroll
                for (int j = 0; j < 8; j++)
                    acc[i][j] = fmaf(a[i], bv[j], acc[i][j]);
        }
        __syncthreads();
    }
    float* Sb = &g_S[b][0][0];
    const float scale = 0.015625f;   // 4096^-0.5
    #pragma unroll
    for (int i = 0; i < 8; i++) {
        int row = i0 + ty * 8 + i;
        float4 o0 = make_float4(acc[i][0] * scale, acc[i][1] * scale,
                                acc[i][2] * scale, acc[i][3] * scale);
        float4 o1 = make_float4(acc[i][4] * scale, acc[i][5] * scale,
                                acc[i][6] * scale, acc[i][7] * scale);
        *(float4*)&Sb[row * TOK + j0 + tx * 8]     = o0;
        *(float4*)&Sb[row * TOK + j0 + tx * 8 + 4] = o1;
    }
}

// ---------------- kernel 3: row softmax over g_S ------------------------------
__global__ __launch_bounds__(128) void softmax_kernel() {
    const int row = blockIdx.x;            // 0..4095
    float* p = &g_S[0][0][0] + (size_t)row * TOK;
    const int tid = threadIdx.x;
    float v[8];
    float m = -1e30f;
    #pragma unroll
    for (int i = 0; i < 8; i++) { v[i] = p[tid + (i << 7)]; m = fmaxf(m, v[i]); }
    #pragma unroll
    for (int o = 16; o > 0; o >>= 1) m = fmaxf(m, __shfl_xor_sync(0xffffffffu, m, o));
    __shared__ float redm[4], reds[4];
    if ((tid & 31) == 0) redm[tid >> 5] = m;
    __syncthreads();
    m = fmaxf(fmaxf(redm[0], redm[1]), fmaxf(redm[2], redm[3]));
    float sum = 0.f;
    #pragma unroll
    for (int i = 0; i < 8; i++) { v[i] = __expf(v[i] - m); sum += v[i]; }
    #pragma unroll
    for (int o = 16; o > 0; o >>= 1) sum += __shfl_xor_sync(0xffffffffu, sum, o);
    if ((tid & 31) == 0) reds[tid >> 5] = sum;
    __syncthreads();
    sum = reds[0] + reds[1] + reds[2] + reds[3];
    float inv = 1.0f / sum;
    #pragma unroll
    for (int i = 0; i < 8; i++) p[tid + (i << 7)] = v[i] * inv;
}

// ---------------- kernel 4: AX = P @ V, NN SGEMM, fold into g_feat ------------
__global__ __launch_bounds__(256, 2) void gemm_av_kernel() {
    __shared__ float As[8][128];
    __shared__ float Bs[8][128];
    const int b  = blockIdx.z;
    const int i0 = blockIdx.y * 128;
    const int d0 = blockIdx.x * 128;
    const int tid = threadIdx.x;
    const int tx = tid & 15;
    const int ty = tid >> 4;
    const float* A  = &g_S[b][0][0];
    const float* Bm = &g_V[b][0][0];
    const int lr = tid >> 1;
    const int lc = (tid & 1) << 2;
    const int br = tid >> 5;
    const int bc = (tid & 31) << 2;
    float acc[8][8];
    #pragma unroll
    for (int i = 0; i < 8; i++)
        #pragma unroll
        for (int j = 0; j < 8; j++) acc[i][j] = 0.f;

    float4 va = *(const float4*)&A [(i0 + lr) * TOK + lc];
    float4 vb = *(const float4*)&Bm[br * DIMD + d0 + bc];
    for (int k0 = 0; k0 < TOK; k0 += 8) {
        As[lc + 0][lr] = va.x; As[lc + 1][lr] = va.y;
        As[lc + 2][lr] = va.z; As[lc + 3][lr] = va.w;
        *(float4*)&Bs[br][bc] = vb;
        __syncthreads();
        if (k0 + 8 < TOK) {
            va = *(const float4*)&A [(i0 + lr) * TOK + k0 + 8 + lc];
            vb = *(const float4*)&Bm[(k0 + 8 + br) * DIMD + d0 + bc];
        }
        #pragma unroll
        for (int kk = 0; kk < 8; kk++) {
            float a[8], bv[8];
            *(float4*)&a[0]  = *(const float4*)&As[kk][ty * 8];
            *(float4*)&a[4]  = *(const float4*)&As[kk][ty * 8 + 4];
            *(float4*)&bv[0] = *(const float4*)&Bs[kk][tx * 8];
            *(float4*)&bv[4] = *(const float4*)&Bs[kk][tx * 8 + 4];
            #pragma unroll
            for (int i = 0; i < 8; i++)
                #pragma unroll
                for (int j = 0; j < 8; j++)
                    acc[i][j] = fmaf(a[i], bv[j], acc[i][j]);
        }
        __syncthreads();
    }
    // fold: token i=(tt,gh,gw), dim d=(oc,pi,pj) -> feat[img][oc][gh*8+pi][gw*8+pj]
    #pragma unroll
    for (int ii = 0; ii < 8; ii++) {
        int i   = i0 + ty * 8 + ii;
        int img = b * 16 + (i >> 6);
        int gh  = (i >> 3) & 7;
        int gw  = i & 7;
        int d   = d0 + tx * 8;
        int oc  = d >> 6;
        int pi  = (d >> 3) & 7;
        float* fp = &g_feat[img][oc][gh * 8 + pi][gw * 8];
        float4 o0 = make_float4(acc[ii][0], acc[ii][1], acc[ii][2], acc[ii][3]);
        float4 o1 = make_float4(acc[ii][4], acc[ii][5], acc[ii][6], acc[ii][7]);
        *(float4*)&fp[0] = o0;
        *(float4*)&fp[4] = o1;
    }
}

// ---------------- kernel 5: final conv (feat * cw + cb) + residual x ----------
__global__ __launch_bounds__(512) void convc_kernel(
    const float* __restrict__ x,
    const float* __restrict__ cb,
    float* __restrict__ out)
{
    extern __shared__ float s[];          // [64][10][66]
    const int img   = blockIdx.x;
    const int ytile = blockIdx.y;
    const int y0    = ytile * 8;
    const int tid   = threadIdx.x;
    const float* fim = &g_feat[img][0][0][0];

    for (int idx = tid; idx < 64 * 10 * 66; idx += 512) {
        int c  = idx / 660;
        int rr = idx - c * 660;
        int yy = rr / 66;
        int xx = rr - yy * 66;
        int gy = y0 - 1 + yy;
        int gx = xx - 1;
        float v = 0.f;
        if (gy >= 0 && gy < 64 && gx >= 0 && gx < 64)
            v = fim[c * 4096 + gy * 64 + gx];
        s[idx] = v;
    }
    __syncthreads();

    const int ocg = tid & 7;
    const int pg  = tid >> 3;
    const int oc0 = ocg << 3;
    const int py  = pg >> 3;
    const int x0  = (pg & 7) << 3;
    float acc[8][8];
    #pragma unroll
    for (int i = 0; i < 8; i++)
        #pragma unroll
        for (int j = 0; j < 8; j++) acc[i][j] = 0.f;

    const float4* wt4 = reinterpret_cast<const float4*>(&g_cwT[0][0]);
    const int wb = oc0 >> 2;
    for (int ic = 0; ic < 64; ic++) {
        const float* sc = s + ic * 660 + py * 66 + x0;
        const float4* wr = wt4 + ic * 144 + wb;
        #pragma unroll
        for (int kk = 0; kk < 9; kk++) {
            const int ky = kk / 3;
            const int kx = kk - ky * 3;
            float4 w0 = wr[kk * 16];
            float4 w1 = wr[kk * 16 + 1];
            float wv[8] = {w0.x, w0.y, w0.z, w0.w, w1.x, w1.y, w1.z, w1.w};
            const float* sp = sc + ky * 66 + kx;
            #pragma unroll
            for (int i = 0; i < 8; i++) {
                float xv = sp[i];
                #pragma unroll
                for (int j = 0; j < 8; j++)
                    acc[i][j] = fmaf(xv, wv[j], acc[i][j]);
            }
        }
    }

    const int yout = y0 + py;
    #pragma unroll
    for (int j = 0; j < 8; j++) {
        int   oc   = oc0 + j;
        float bias = cb[oc];
        int   base = ((img * 64 + oc) * 64 + yout) * 64 + x0;
        float4 xr0 = *(const float4*)&x[base];
        float4 xr1 = *(const float4*)&x[base + 4];
        float4 o0  = make_float4(acc[0][j] + bias + xr0.x, acc[1][j] + bias + xr0.y,
                                 acc[2][j] + bias + xr0.z, acc[3][j] + bias + xr0.w);
        float4 o1  = make_float4(acc[4][j] + bias + xr1.x, acc[5][j] + bias + xr1.y,
                                 acc[6][j] + bias + xr1.z, acc[7][j] + bias + xr1.w);
        *(float4*)&out[base]     = o0;
        *(float4*)&out[base + 4] = o1;
    }
}

// ---------------- launcher ----------------------------------------------------
extern "C" void kernel_launch(void* const* d_in, const int* in_sizes, int n_in,
                              void* d_out, int out_size) {
    (void)in_sizes; (void)n_in; (void)out_size;
    const float* x  = (const float*)d_in[0];
    const float* qw = (const float*)d_in[1];
    const float* qb = (const float*)d_in[2];
    const float* kw = (const float*)d_in[3];
    const float* kb = (const float*)d_in[4];
    const float* vw = (const float*)d_in[5];
    const float* vb = (const float*)d_in[6];
    const float* cw = (const float*)d_in[7];
    const float* cb = (const float*)d_in[8];
    float* out = (float*)d_out;

    const int smem = 64 * 10 * 66 * sizeof(float);   // 168,960 B
    cudaFuncSetAttribute(qkv_kernel,   cudaFuncAttributeMaxDynamicSharedMemorySize, smem);
    cudaFuncSetAttribute(convc_kernel, cudaFuncAttributeMaxDynamicSharedMemorySize, smem);

    transpose_w_kernel<<<(64 * 576 + 255) / 256, 256>>>(vw, cw);
    qkv_kernel<<<dim3(64, 8), 512, smem>>>(x, qw, qb, kw, kb, vb);
    gemm_qk_kernel<<<dim3(8, 8, NB), 256>>>();
    softmax_kernel<<<NB * TOK, 128>>>();
    gemm_av_kernel<<<dim3(32, 8, NB), 256>>>();
    convc_kernel<<<dim3(64, 8), 512, smem>>>(x, cb, out);
}